// round 13
// baseline (speedup 1.0000x reference)
#include <cuda_runtime.h>

// ---------------- Problem constants ----------------
#define NMAX 100352          // >= 100000 nodes
#define EMAX 1700000         // >= 1.6M edges
#define FEAT 128             // F == H == 128

// ---------------- Device scratch (no allocs allowed) ----------------
__device__ int   g_is64;
__device__ int   g_oddnz;
__device__ int   g_cnt[NMAX];
__device__ float g_summ[NMAX];
__device__ int   g_rowptr[NMAX + 1];
__device__ int   g_wcur[NMAX];
__device__ int   g_colind[EMAX];
__device__ int   g_bsum[512];
__device__ int   g_boff[512];
__device__ float2 g_dlh[NMAX];            // packed (dl, dh)
__device__ float g_dll[NMAX], g_dhh[NMAX];
__device__ float g_wll[NMAX], g_whh[NMAX];
__device__ float g_bufA[NMAX * FEAT];
__device__ float g_bufB[NMAX * FEAT];
__device__ float g_bufC[NMAX * FEAT];
__device__ float g_bufD[NMAX * FEAT];
__device__ float g_bufE[NMAX * FEAT];
// weight fragments: 5 weights x 8192 float4 (16 ksteps x 16 tiles x 32 lanes)
// float4 = {hi(b0), hi(b1), lo(b0), lo(b1)}
__device__ float4 g_wf[5 * 8192];

// ---------------- tf32 helpers -----------------
__device__ __forceinline__ float tf32r(float x) {
    unsigned u;
    asm("cvt.rna.tf32.f32 %0, %1;" : "=r"(u) : "f"(x));
    return __uint_as_float(u);
}

__device__ __forceinline__ void mma8(float4& d,
                                     unsigned a0, unsigned a1, unsigned a2, unsigned a3,
                                     unsigned b0, unsigned b1) {
    asm("mma.sync.aligned.m16n8k8.row.col.f32.tf32.tf32.f32 "
        "{%0,%1,%2,%3}, {%4,%5,%6,%7}, {%8,%9}, {%0,%1,%2,%3};"
        : "+f"(d.x), "+f"(d.y), "+f"(d.z), "+f"(d.w)
        : "r"(a0), "r"(a1), "r"(a2), "r"(a3), "r"(b0), "r"(b1));
}

// ---------------- dtype detector: int32 vs int64 edge_index -------------
__global__ void detectK(const int* __restrict__ ei, int nwords) {
    if (threadIdx.x == 0) g_oddnz = 0;
    __syncthreads();
    int lim = nwords < 4096 ? nwords : 4096;
    for (int i = 1 + 2 * (int)threadIdx.x; i < lim; i += 2 * (int)blockDim.x)
        if (ei[i] != 0) atomicOr(&g_oddnz, 1);
    __syncthreads();
    if (threadIdx.x == 0) g_is64 = (g_oddnz == 0) ? 1 : 0;
}

__device__ __forceinline__ void edge_fetch(const int* ei, int E, int e,
                                           int& s, int& r) {
    if (g_is64) {          // int64 little-endian: low words at even positions
        s = ei[2 * e];
        r = ei[2 * E + 2 * e];
    } else {               // int32: [src x E, dst x E]
        s = ei[e];
        r = ei[E + e];
    }
}

// ---------------- weight fragment prep: 5 weights -> g_wf ----------------
// Fragment semantics (m16n8k8.row.col): lane = 4g+t holds
//   b0 = W[ksg*8 + t][tile*8 + g], b1 = W[ksg*8 + t + 4][tile*8 + g]
__global__ void wprepK(const float* __restrict__ W1L, const float* __restrict__ W1H,
                       const float* __restrict__ W2L, const float* __restrict__ W2H,
                       const float* __restrict__ WX) {
    const float* Ws[5] = {W1L, W1H, W2L, W2H, WX};
    int widx = blockIdx.y;
    const float* W = Ws[widx];
    int base = blockIdx.x * 512;          // 16 blocks x 512 float4 = 8192
    for (int i = 0; i < 2; i++) {
        int idx = base + threadIdx.x + i * 256;
        int lane = idx & 31;
        int tile = (idx >> 5) & 15;
        int ksg  = idx >> 9;
        int g = lane >> 2, t = lane & 3;
        float b0 = W[(ksg * 8 + t) * 128 + tile * 8 + g];
        float b1 = W[(ksg * 8 + t + 4) * 128 + tile * 8 + g];
        float h0 = tf32r(b0), h1 = tf32r(b1);
        float l0 = tf32r(b0 - h0), l1 = tf32r(b1 - h1);
        g_wf[widx * 8192 + idx] = make_float4(h0, h1, l0, l1);
    }
}

// ---------------- Preprocessing ----------------
__global__ void initK(int n) {
    int i = blockIdx.x * blockDim.x + threadIdx.x;
    if (i < n) { g_cnt[i] = 0; g_summ[i] = 0.f; }
}

__global__ void countK(const int* __restrict__ ei,
                       const float* __restrict__ cc, int E, int n) {
    int e = blockIdx.x * blockDim.x + threadIdx.x;
    if (e >= E) return;
    int s, r;
    edge_fetch(ei, E, e, s, r);
    if (s != r && (unsigned)s < (unsigned)n && (unsigned)r < (unsigned)n) {
        atomicAdd(&g_cnt[r], 1);
        atomicAdd(&g_summ[r], cc[s]);
    }
}

// ---------------- 3-phase grid scan over g_cnt -> rowptr, wcur ----------
__global__ void bsumK(int n) {
    __shared__ int sh[256];
    int t = threadIdx.x;
    int i = blockIdx.x * 256 + t;
    int v = (i < n) ? g_cnt[i] : 0;
    sh[t] = v;
    __syncthreads();
    for (int s = 128; s > 0; s >>= 1) {
        if (t < s) sh[t] += sh[t + s];
        __syncthreads();
    }
    if (t == 0) g_bsum[blockIdx.x] = sh[0];
}

__global__ void bscanK(int nb, int n) {   // 1 block, 512 threads
    __shared__ int sh[512];
    int t = threadIdx.x;
    int v = (t < nb) ? g_bsum[t] : 0;
    sh[t] = v;
    __syncthreads();
    for (int off = 1; off < 512; off <<= 1) {
        int u = (t >= off) ? sh[t - off] : 0;
        __syncthreads();
        sh[t] += u;
        __syncthreads();
    }
    g_boff[t] = sh[t] - v;                 // exclusive prefix
    if (t == 0) g_rowptr[n] = sh[511];     // grand total
}

__global__ void bfinalK(int n) {
    __shared__ int sh[256];
    int t = threadIdx.x;
    int i = blockIdx.x * 256 + t;
    int v = (i < n) ? g_cnt[i] : 0;
    sh[t] = v;
    __syncthreads();
    for (int off = 1; off < 256; off <<= 1) {
        int u = (t >= off) ? sh[t - off] : 0;
        __syncthreads();
        sh[t] += u;
        __syncthreads();
    }
    int excl = sh[t] - v + g_boff[blockIdx.x];
    if (i < n) { g_rowptr[i] = excl; g_wcur[i] = excl; }
}

__global__ void dinvK(const float* __restrict__ cc, int n) {
    int i = blockIdx.x * blockDim.x + threadIdx.x;
    if (i >= n) return;
    float m   = cc[i];
    float cnt = (float)g_cnt[i];
    float sm  = g_summ[i];
    float dl  = rsqrtf(m * cnt + 1.f);
    float dh  = rsqrtf((1.f - m) * cnt + 1.f);
    float dll = rsqrtf(sm + 1.f);
    float dhh = rsqrtf(cnt - sm + 1.f);
    g_dlh[i] = make_float2(dl, dh);
    g_dll[i] = dll; g_dhh[i] = dhh;
    g_wll[i] = m * dll;
    g_whh[i] = (1.f - m) * dhh;
}

__global__ void scatterK(const int* __restrict__ ei, int E, int n) {
    int e = blockIdx.x * blockDim.x + threadIdx.x;
    if (e >= E) return;
    int s, r;
    edge_fetch(ei, E, e, s, r);
    if (s != r && (unsigned)s < (unsigned)n && (unsigned)r < (unsigned)n) {
        int pos = atomicAdd(&g_wcur[r], 1);
        g_colind[pos] = s;
    }
}

// ---------------- SpMM layer 1: warp per destination row (fused low+high) ---
__global__ void __launch_bounds__(256) spmm1K(const float* __restrict__ x,
                                              const float* __restrict__ cc, int n) {
    int w = (blockIdx.x * blockDim.x + threadIdx.x) >> 5;
    int lane = threadIdx.x & 31;
    if (w >= n) return;
    const float4* x4 = (const float4*)x;
    float4 al = make_float4(0.f, 0.f, 0.f, 0.f);
    float4 ah = make_float4(0.f, 0.f, 0.f, 0.f);
    int s = g_rowptr[w], e = g_rowptr[w + 1];
    for (int i = s; i < e; i++) {
        int c = g_colind[i];
        float2 wlh = g_dlh[c];
        float4 xv = __ldg(&x4[c * 32 + lane]);
        al.x = fmaf(wlh.x, xv.x, al.x); al.y = fmaf(wlh.x, xv.y, al.y);
        al.z = fmaf(wlh.x, xv.z, al.z); al.w = fmaf(wlh.x, xv.w, al.w);
        ah.x = fmaf(wlh.y, xv.x, ah.x); ah.y = fmaf(wlh.y, xv.y, ah.y);
        ah.z = fmaf(wlh.y, xv.z, ah.z); ah.w = fmaf(wlh.y, xv.w, ah.w);
    }
    float m = cc[w];
    float2 dlh = g_dlh[w];
    float4 xr = x4[w * 32 + lane];
    float sl = dlh.x * m, dl2 = dlh.x * dlh.x;
    float sh = dlh.y * (1.f - m), dh2 = dlh.y * dlh.y;
    float4 ol, oh;
    ol.x = fmaf(sl, al.x, dl2 * xr.x); ol.y = fmaf(sl, al.y, dl2 * xr.y);
    ol.z = fmaf(sl, al.z, dl2 * xr.z); ol.w = fmaf(sl, al.w, dl2 * xr.w);
    oh.x = fmaf(sh, ah.x, dh2 * xr.x); oh.y = fmaf(sh, ah.y, dh2 * xr.y);
    oh.z = fmaf(sh, ah.z, dh2 * xr.z); oh.w = fmaf(sh, ah.w, dh2 * xr.w);
    ((float4*)g_bufA)[w * 32 + lane] = ol;
    ((float4*)g_bufB)[w * 32 + lane] = oh;
}

// ---------------- SpMM layer 2, fused low+high (shared index walk) ----------
__global__ void __launch_bounds__(256) spmm2F(int n) {
    int w = (blockIdx.x * blockDim.x + threadIdx.x) >> 5;
    int lane = threadIdx.x & 31;
    if (w >= n) return;
    const float4* c4 = (const float4*)g_bufC;
    const float4* d4 = (const float4*)g_bufD;
    float4 accC = make_float4(0.f, 0.f, 0.f, 0.f);
    float4 accD = make_float4(0.f, 0.f, 0.f, 0.f);
    int s = g_rowptr[w], e = g_rowptr[w + 1];
    for (int i = s; i < e; i++) {
        int c = g_colind[i];
        float wl = g_wll[c];
        float wh = g_whh[c];
        float4 cv = __ldg(&c4[c * 32 + lane]);
        float4 dv = __ldg(&d4[c * 32 + lane]);
        accC.x = fmaf(wl, cv.x, accC.x); accC.y = fmaf(wl, cv.y, accC.y);
        accC.z = fmaf(wl, cv.z, accC.z); accC.w = fmaf(wl, cv.w, accC.w);
        accD.x = fmaf(wh, dv.x, accD.x); accD.y = fmaf(wh, dv.y, accD.y);
        accD.z = fmaf(wh, dv.z, accD.z); accD.w = fmaf(wh, dv.w, accD.w);
    }
    float dl = g_dll[w], dl2 = dl * dl;
    float dh = g_dhh[w], dh2 = dh * dh;
    float4 cr = c4[w * 32 + lane];
    float4 dr = d4[w * 32 + lane];
    float4 oa, ob;
    oa.x = fmaf(dl, accC.x, dl2 * cr.x); oa.y = fmaf(dl, accC.y, dl2 * cr.y);
    oa.z = fmaf(dl, accC.z, dl2 * cr.z); oa.w = fmaf(dl, accC.w, dl2 * cr.w);
    ob.x = fmaf(dh, accD.x, dh2 * dr.x); ob.y = fmaf(dh, accD.y, dh2 * dr.y);
    ob.z = fmaf(dh, accD.z, dh2 * dr.z); ob.w = fmaf(dh, accD.w, dh2 * dr.w);
    ((float4*)g_bufA)[w * 32 + lane] = oa;
    ((float4*)g_bufB)[w * 32 + lane] = ob;
}

// ---------------- GEMM: [n x 64-row tiles] @ [128 x 128] via 3xTF32 mma -----
// Block = 64 rows, 8 warps. Warp (wid) owns 16 rows (wid>>1) x 64 cols (wid&1):
// 8 n8-tiles -> acc = 32 regs. Weight fragments via __ldg from g_wf (L1-hot).
// A staged per 32-k chunk in fragment-ordered smem (8 KB).
// D += Ahi*Bhi + Ahi*Blo + Alo*Bhi  (3xTF32: fp32-grade accuracy).
// ASRC: 0=g_bufA, 1=g_bufB, 2=external (x). CDST: 0=g_bufC, 1=g_bufD, 2=g_bufE.
template<int ASRC, int CDST, int WIDX, bool RELU>
__global__ void __launch_bounds__(256, 2) gemmT(const float* __restrict__ Aext,
                                                int n) {
    const float* A = (ASRC == 0) ? g_bufA : (ASRC == 1) ? g_bufB : Aext;
    float* C       = (CDST == 0) ? g_bufC : (CDST == 1) ? g_bufD : g_bufE;
    const float4* WF = g_wf + WIDX * 8192;

    __shared__ float sA[2048];     // 8 KB: [rowg(4)][ks(4)][lane(32)][j(4)]

    int tid  = threadIdx.x;
    int wid  = tid >> 5;
    int lane = tid & 31;
    int g    = lane >> 2;     // group id (row / n offset)
    int t    = lane & 3;      // thread-in-group (k offset)

    int rowg = wid >> 1;          // row group 0..3 (16 rows each)
    int ch   = wid & 1;           // column half 0..1 (64 cols each)

    int rowB = blockIdx.x * 64;
    int rA = rowB + rowg * 16 + g;
    int rB = rA + 8;
    bool v0 = rA < n, v1 = rB < n;

    float4 acc[8];
    #pragma unroll
    for (int i = 0; i < 8; i++) acc[i] = make_float4(0.f, 0.f, 0.f, 0.f);

    const float4* A4 = (const float4*)A;

    for (int chunk = 0; chunk < 4; chunk++) {
        __syncthreads();
        // ---- stage A chunk (64 rows x 32 k) coalesced -> fragment layout
        #pragma unroll
        for (int i = 0; i < 2; i++) {
            int idx = tid + i * 256;        // 0..511
            int r = idx >> 3;               // row within tile 0..63
            int q = idx & 7;                // float4 index within 32-k chunk
            float4 v = (rowB + r < n) ? A4[(rowB + r) * 32 + chunk * 8 + q]
                                      : make_float4(0.f, 0.f, 0.f, 0.f);
            int rg = r >> 4;                // row group
            int rw = r & 15;
            int gp = rw & 7, half = rw >> 3;
            #pragma unroll
            for (int j = 0; j < 4; j++) {
                int k = 4 * q + j;
                int ks = k >> 3, kk = k & 7;
                int addr = ((rg * 4 + ks) * 32 + gp * 4 + (kk & 3)) * 4
                         + (half + 2 * (kk >> 2));
                float val = (j == 0) ? v.x : (j == 1) ? v.y : (j == 2) ? v.z : v.w;
                sA[addr] = val;
            }
        }
        __syncthreads();

        #pragma unroll
        for (int ksl = 0; ksl < 4; ksl++) {
            int ks = chunk * 4 + ksl;       // global k-step 0..15
            float4 a = *(const float4*)&sA[((rowg * 4 + ksl) * 32 + lane) * 4];
            float h0 = tf32r(a.x), h1 = tf32r(a.y), h2 = tf32r(a.z), h3 = tf32r(a.w);
            float l0 = tf32r(a.x - h0), l1 = tf32r(a.y - h1);
            float l2 = tf32r(a.z - h2), l3 = tf32r(a.w - h3);
            unsigned ah0 = __float_as_uint(h0), ah1 = __float_as_uint(h1);
            unsigned ah2 = __float_as_uint(h2), ah3 = __float_as_uint(h3);
            unsigned al0 = __float_as_uint(l0), al1 = __float_as_uint(l1);
            unsigned al2 = __float_as_uint(l2), al3 = __float_as_uint(l3);

            // (ks*16 + ch*8 + tile)*32 + lane
            const float4* wf = WF + ks * 512 + ch * 256 + lane;
            #pragma unroll
            for (int tile = 0; tile < 8; tile++) {
                float4 f = __ldg(wf + tile * 32);
                unsigned bh0 = __float_as_uint(f.x), bh1 = __float_as_uint(f.y);
                unsigned bl0 = __float_as_uint(f.z), bl1 = __float_as_uint(f.w);
                mma8(acc[tile], ah0, ah1, ah2, ah3, bh0, bh1);   // hi*hi
                mma8(acc[tile], ah0, ah1, ah2, ah3, bl0, bl1);   // hi*lo
                mma8(acc[tile], al0, al1, al2, al3, bh0, bh1);   // lo*hi
            }
        }
    }

    // store: c0,c1 -> (rA, ch*64 + tile*8 + 2t); c2,c3 -> (rB, same cols)
    #pragma unroll
    for (int tile = 0; tile < 8; tile++) {
        float2 o0 = make_float2(acc[tile].x, acc[tile].y);
        float2 o1 = make_float2(acc[tile].z, acc[tile].w);
        if (RELU) {
            o0.x = fmaxf(o0.x, 0.f); o0.y = fmaxf(o0.y, 0.f);
            o1.x = fmaxf(o1.x, 0.f); o1.y = fmaxf(o1.y, 0.f);
        }
        int col = ch * 64 + tile * 8 + 2 * t;
        if (v0) *(float2*)(C + rA * 128 + col) = o0;
        if (v1) *(float2*)(C + rB * 128 + col) = o1;
    }
}

// ---------------- Fused epilogue: gate + relu + [128x10] projection ----------
__global__ void __launch_bounds__(256) epiK(const float* __restrict__ cc,
                                            const float* __restrict__ lam1,
                                            const float* __restrict__ lam2,
                                            const float* __restrict__ lw,
                                            const float* __restrict__ lb,
                                            float* __restrict__ out, int n) {
    __shared__ float sw[1280];
    int tid = threadIdx.x;
    for (int i = tid; i < 1280; i += 256) sw[i] = lw[i];
    __syncthreads();
    int w = (blockIdx.x << 3) + (tid >> 5);
    int lane = tid & 31;
    if (w >= n) return;

    float lamxl = 1.f / (1.f + expf(lam1[1] - lam1[0]));
    float laml  = 1.f - lamxl;
    float lamxh = 1.f / (1.f + expf(lam2[1] - lam2[0]));
    float lamh  = 1.f - lamxh;
    float m = cc[w];
    float lamx = lamxl * m + lamxh * (1.f - m);

    float4 fc = ((const float4*)g_bufE)[w * 32 + lane];
    float4 fl = ((const float4*)g_bufC)[w * 32 + lane];
    float4 fh = ((const float4*)g_bufD)[w * 32 + lane];
    float4 g;
    g.x = fmaxf(0.f, lamx * fc.x + laml * fl.x + lamh * fh.x);
    g.y = fmaxf(0.f, lamx * fc.y + laml * fl.y + lamh * fh.y);
    g.z = fmaxf(0.f, lamx * fc.z + laml * fl.z + lamh * fh.z);
    g.w = fmaxf(0.f, lamx * fc.w + laml * fl.w + lamh * fh.w);

    int base = lane * 40;  // (lane*4) * 10
    #pragma unroll
    for (int c = 0; c < 10; c++) {
        float p = g.x * sw[base + c] + g.y * sw[base + 10 + c] +
                  g.z * sw[base + 20 + c] + g.w * sw[base + 30 + c];
        #pragma unroll
        for (int off = 16; off > 0; off >>= 1)
            p += __shfl_xor_sync(0xffffffffu, p, off);
        if (lane == 0) out[w * 10 + c] = p + lb[c];
    }
}

// ---------------- Launch (kernel launches ONLY, no host API) ----------------
extern "C" void kernel_launch(void* const* d_in, const int* in_sizes, int n_in,
                              void* d_out, int out_size) {
    const float* x    = (const float*)d_in[0];
    const int*   ei   = (const int*)d_in[1];       // int32 (or int64 low-words; detected)
    const float* cc   = (const float*)d_in[2];
    const float* W1L  = (const float*)d_in[3];
    const float* W1H  = (const float*)d_in[4];
    const float* W2L  = (const float*)d_in[5];
    const float* W2H  = (const float*)d_in[6];
    const float* WX   = (const float*)d_in[7];
    const float* lam1 = (const float*)d_in[8];
    const float* lam2 = (const float*)d_in[9];
    const float* lw   = (const float*)d_in[10];
    const float* lb   = (const float*)d_in[11];
    float*       out  = (float*)d_out;

    int n = in_sizes[2];        // cc_mask element count == N
    int E = in_sizes[1] / 2;    // element count / 2, dtype-independent

    int nbN = (n + 255) / 256;
    int nbE = (E + 255) / 256;
    int nbW = (n + 7) / 8;      // warp-per-row kernels, 8 warps/block
    int nbG = (n + 63) / 64;    // GEMM 64-row tiles

    // order chosen so launch index 3 (the ncu sample) is a gemmT
    detectK<<<1, 256>>>(ei, in_sizes[1]);                       // 0
    initK<<<nbN, 256>>>(n);                                     // 1
    wprepK<<<dim3(16, 5), 256>>>(W1L, W1H, W2L, W2H, WX);       // 2
    gemmT<2, 2, 4, false><<<nbG, 256>>>(x, n);                  // 3: bufE = x@WX (profiled)
    countK<<<nbE, 256>>>(ei, cc, E, n);                         // 4
    bsumK<<<nbN, 256>>>(n);                                     // 5
    bscanK<<<1, 512>>>(nbN, n);                                 // 6
    bfinalK<<<nbN, 256>>>(n);                                   // 7
    dinvK<<<nbN, 256>>>(cc, n);                                 // 8
    scatterK<<<nbE, 256>>>(ei, E, n);                           // 9

    spmm1K<<<nbW, 256>>>(x, cc, n);                             // -> bufA, bufB
    gemmT<0, 0, 0, true ><<<nbG, 256>>>(nullptr, n);            // bufC = relu(bufA@W1L)
    gemmT<1, 1, 1, true ><<<nbG, 256>>>(nullptr, n);            // bufD = relu(bufB@W1H)
    spmm2F<<<nbW, 256>>>(n);                                    // bufA, bufB
    gemmT<0, 0, 2, false><<<nbG, 256>>>(nullptr, n);            // bufC = bufA@W2L (xl)
    gemmT<1, 1, 3, false><<<nbG, 256>>>(nullptr, n);            // bufD = bufB@W2H (xh)
    epiK<<<nbW, 256>>>(cc, lam1, lam2, lw, lb, out, n);
}

// round 14
// speedup vs baseline: 1.3626x; 1.3626x over previous
#include <cuda_runtime.h>

// ---------------- Problem constants ----------------
#define NMAX 100352          // >= 100000 nodes
#define EMAX 1700000         // >= 1.6M edges
#define FEAT 128             // F == H == 128

// ---------------- Device scratch (no allocs allowed) ----------------
__device__ int   g_is64;
__device__ int   g_oddnz;
__device__ int   g_cnt[NMAX];
__device__ float g_summ[NMAX];
__device__ int   g_rowptr[NMAX + 1];
__device__ int   g_wcur[NMAX];
__device__ int   g_colind[EMAX];
__device__ int   g_bsum[512];
__device__ int   g_boff[512];
__device__ float2 g_dlh[NMAX];            // packed (dl, dh)
__device__ float g_dll[NMAX], g_dhh[NMAX];
__device__ float g_wll[NMAX], g_whh[NMAX];
__device__ float g_bufA[NMAX * FEAT];
__device__ float g_bufB[NMAX * FEAT];
__device__ float g_bufC[NMAX * FEAT];
__device__ float g_bufD[NMAX * FEAT];
__device__ float g_bufE[NMAX * FEAT];
// weight fragments: 5 weights x 8192 float4 (16 ksteps x 16 tiles x 32 lanes)
// float4 = {hi(b0), hi(b1), lo(b0), lo(b1)}
__device__ float4 g_wf[5 * 8192];

// ---------------- tf32 helpers -----------------
__device__ __forceinline__ float tf32r(float x) {
    unsigned u;
    asm("cvt.rna.tf32.f32 %0, %1;" : "=r"(u) : "f"(x));
    return __uint_as_float(u);
}

__device__ __forceinline__ void mma8(float4& d,
                                     unsigned a0, unsigned a1, unsigned a2, unsigned a3,
                                     unsigned b0, unsigned b1) {
    asm("mma.sync.aligned.m16n8k8.row.col.f32.tf32.tf32.f32 "
        "{%0,%1,%2,%3}, {%4,%5,%6,%7}, {%8,%9}, {%0,%1,%2,%3};"
        : "+f"(d.x), "+f"(d.y), "+f"(d.z), "+f"(d.w)
        : "r"(a0), "r"(a1), "r"(a2), "r"(a3), "r"(b0), "r"(b1));
}

// ---------------- dtype detector: int32 vs int64 edge_index -------------
__global__ void detectK(const int* __restrict__ ei, int nwords) {
    if (threadIdx.x == 0) g_oddnz = 0;
    __syncthreads();
    int lim = nwords < 4096 ? nwords : 4096;
    for (int i = 1 + 2 * (int)threadIdx.x; i < lim; i += 2 * (int)blockDim.x)
        if (ei[i] != 0) atomicOr(&g_oddnz, 1);
    __syncthreads();
    if (threadIdx.x == 0) g_is64 = (g_oddnz == 0) ? 1 : 0;
}

__device__ __forceinline__ void edge_fetch(const int* ei, int E, int e,
                                           int& s, int& r) {
    if (g_is64) {          // int64 little-endian: low words at even positions
        s = ei[2 * e];
        r = ei[2 * E + 2 * e];
    } else {               // int32: [src x E, dst x E]
        s = ei[e];
        r = ei[E + e];
    }
}

// ---------------- weight fragment prep: 5 weights -> g_wf ----------------
// Fragment semantics (m16n8k8.row.col): lane = 4g+t holds
//   b0 = W[ksg*8 + t][tile*8 + g], b1 = W[ksg*8 + t + 4][tile*8 + g]
__global__ void wprepK(const float* __restrict__ W1L, const float* __restrict__ W1H,
                       const float* __restrict__ W2L, const float* __restrict__ W2H,
                       const float* __restrict__ WX) {
    const float* Ws[5] = {W1L, W1H, W2L, W2H, WX};
    int widx = blockIdx.y;
    const float* W = Ws[widx];
    int base = blockIdx.x * 512;          // 16 blocks x 512 float4 = 8192
    for (int i = 0; i < 2; i++) {
        int idx = base + threadIdx.x + i * 256;
        int lane = idx & 31;
        int tile = (idx >> 5) & 15;
        int ksg  = idx >> 9;
        int g = lane >> 2, t = lane & 3;
        float b0 = W[(ksg * 8 + t) * 128 + tile * 8 + g];
        float b1 = W[(ksg * 8 + t + 4) * 128 + tile * 8 + g];
        float h0 = tf32r(b0), h1 = tf32r(b1);
        float l0 = tf32r(b0 - h0), l1 = tf32r(b1 - h1);
        g_wf[widx * 8192 + idx] = make_float4(h0, h1, l0, l1);
    }
}

// ---------------- Preprocessing ----------------
__global__ void initK(int n) {
    int i = blockIdx.x * blockDim.x + threadIdx.x;
    if (i < n) { g_cnt[i] = 0; g_summ[i] = 0.f; }
}

__global__ void countK(const int* __restrict__ ei,
                       const float* __restrict__ cc, int E, int n) {
    int e = blockIdx.x * blockDim.x + threadIdx.x;
    if (e >= E) return;
    int s, r;
    edge_fetch(ei, E, e, s, r);
    if (s != r && (unsigned)s < (unsigned)n && (unsigned)r < (unsigned)n) {
        atomicAdd(&g_cnt[r], 1);
        atomicAdd(&g_summ[r], cc[s]);
    }
}

// ---------------- 3-phase grid scan over g_cnt -> rowptr, wcur ----------
__global__ void bsumK(int n) {
    __shared__ int sh[256];
    int t = threadIdx.x;
    int i = blockIdx.x * 256 + t;
    int v = (i < n) ? g_cnt[i] : 0;
    sh[t] = v;
    __syncthreads();
    for (int s = 128; s > 0; s >>= 1) {
        if (t < s) sh[t] += sh[t + s];
        __syncthreads();
    }
    if (t == 0) g_bsum[blockIdx.x] = sh[0];
}

__global__ void bscanK(int nb, int n) {   // 1 block, 512 threads
    __shared__ int sh[512];
    int t = threadIdx.x;
    int v = (t < nb) ? g_bsum[t] : 0;
    sh[t] = v;
    __syncthreads();
    for (int off = 1; off < 512; off <<= 1) {
        int u = (t >= off) ? sh[t - off] : 0;
        __syncthreads();
        sh[t] += u;
        __syncthreads();
    }
    g_boff[t] = sh[t] - v;                 // exclusive prefix
    if (t == 0) g_rowptr[n] = sh[511];     // grand total
}

__global__ void bfinalK(int n) {
    __shared__ int sh[256];
    int t = threadIdx.x;
    int i = blockIdx.x * 256 + t;
    int v = (i < n) ? g_cnt[i] : 0;
    sh[t] = v;
    __syncthreads();
    for (int off = 1; off < 256; off <<= 1) {
        int u = (t >= off) ? sh[t - off] : 0;
        __syncthreads();
        sh[t] += u;
        __syncthreads();
    }
    int excl = sh[t] - v + g_boff[blockIdx.x];
    if (i < n) { g_rowptr[i] = excl; g_wcur[i] = excl; }
}

__global__ void dinvK(const float* __restrict__ cc, int n) {
    int i = blockIdx.x * blockDim.x + threadIdx.x;
    if (i >= n) return;
    float m   = cc[i];
    float cnt = (float)g_cnt[i];
    float sm  = g_summ[i];
    float dl  = rsqrtf(m * cnt + 1.f);
    float dh  = rsqrtf((1.f - m) * cnt + 1.f);
    float dll = rsqrtf(sm + 1.f);
    float dhh = rsqrtf(cnt - sm + 1.f);
    g_dlh[i] = make_float2(dl, dh);
    g_dll[i] = dll; g_dhh[i] = dhh;
    g_wll[i] = m * dll;
    g_whh[i] = (1.f - m) * dhh;
}

__global__ void scatterK(const int* __restrict__ ei, int E, int n) {
    int e = blockIdx.x * blockDim.x + threadIdx.x;
    if (e >= E) return;
    int s, r;
    edge_fetch(ei, E, e, s, r);
    if (s != r && (unsigned)s < (unsigned)n && (unsigned)r < (unsigned)n) {
        int pos = atomicAdd(&g_wcur[r], 1);
        g_colind[pos] = s;
    }
}

// ---------------- SpMM layer 1: warp per destination row (fused low+high) ---
__global__ void __launch_bounds__(256) spmm1K(const float* __restrict__ x,
                                              const float* __restrict__ cc, int n) {
    int w = (blockIdx.x * blockDim.x + threadIdx.x) >> 5;
    int lane = threadIdx.x & 31;
    if (w >= n) return;
    const float4* x4 = (const float4*)x;
    float4 al = make_float4(0.f, 0.f, 0.f, 0.f);
    float4 ah = make_float4(0.f, 0.f, 0.f, 0.f);
    int s = g_rowptr[w], e = g_rowptr[w + 1];
    for (int i = s; i < e; i++) {
        int c = g_colind[i];
        float2 wlh = g_dlh[c];
        float4 xv = __ldg(&x4[c * 32 + lane]);
        al.x = fmaf(wlh.x, xv.x, al.x); al.y = fmaf(wlh.x, xv.y, al.y);
        al.z = fmaf(wlh.x, xv.z, al.z); al.w = fmaf(wlh.x, xv.w, al.w);
        ah.x = fmaf(wlh.y, xv.x, ah.x); ah.y = fmaf(wlh.y, xv.y, ah.y);
        ah.z = fmaf(wlh.y, xv.z, ah.z); ah.w = fmaf(wlh.y, xv.w, ah.w);
    }
    float m = cc[w];
    float2 dlh = g_dlh[w];
    float4 xr = x4[w * 32 + lane];
    float sl = dlh.x * m, dl2 = dlh.x * dlh.x;
    float sh = dlh.y * (1.f - m), dh2 = dlh.y * dlh.y;
    float4 ol, oh;
    ol.x = fmaf(sl, al.x, dl2 * xr.x); ol.y = fmaf(sl, al.y, dl2 * xr.y);
    ol.z = fmaf(sl, al.z, dl2 * xr.z); ol.w = fmaf(sl, al.w, dl2 * xr.w);
    oh.x = fmaf(sh, ah.x, dh2 * xr.x); oh.y = fmaf(sh, ah.y, dh2 * xr.y);
    oh.z = fmaf(sh, ah.z, dh2 * xr.z); oh.w = fmaf(sh, ah.w, dh2 * xr.w);
    ((float4*)g_bufA)[w * 32 + lane] = ol;
    ((float4*)g_bufB)[w * 32 + lane] = oh;
}

// ---------------- SpMM layer 2, fused low+high (shared index walk) ----------
__global__ void __launch_bounds__(256) spmm2F(int n) {
    int w = (blockIdx.x * blockDim.x + threadIdx.x) >> 5;
    int lane = threadIdx.x & 31;
    if (w >= n) return;
    const float4* c4 = (const float4*)g_bufC;
    const float4* d4 = (const float4*)g_bufD;
    float4 accC = make_float4(0.f, 0.f, 0.f, 0.f);
    float4 accD = make_float4(0.f, 0.f, 0.f, 0.f);
    int s = g_rowptr[w], e = g_rowptr[w + 1];
    for (int i = s; i < e; i++) {
        int c = g_colind[i];
        float wl = g_wll[c];
        float wh = g_whh[c];
        float4 cv = __ldg(&c4[c * 32 + lane]);
        float4 dv = __ldg(&d4[c * 32 + lane]);
        accC.x = fmaf(wl, cv.x, accC.x); accC.y = fmaf(wl, cv.y, accC.y);
        accC.z = fmaf(wl, cv.z, accC.z); accC.w = fmaf(wl, cv.w, accC.w);
        accD.x = fmaf(wh, dv.x, accD.x); accD.y = fmaf(wh, dv.y, accD.y);
        accD.z = fmaf(wh, dv.z, accD.z); accD.w = fmaf(wh, dv.w, accD.w);
    }
    float dl = g_dll[w], dl2 = dl * dl;
    float dh = g_dhh[w], dh2 = dh * dh;
    float4 cr = c4[w * 32 + lane];
    float4 dr = d4[w * 32 + lane];
    float4 oa, ob;
    oa.x = fmaf(dl, accC.x, dl2 * cr.x); oa.y = fmaf(dl, accC.y, dl2 * cr.y);
    oa.z = fmaf(dl, accC.z, dl2 * cr.z); oa.w = fmaf(dl, accC.w, dl2 * cr.w);
    ob.x = fmaf(dh, accD.x, dh2 * dr.x); ob.y = fmaf(dh, accD.y, dh2 * dr.y);
    ob.z = fmaf(dh, accD.z, dh2 * dr.z); ob.w = fmaf(dh, accD.w, dh2 * dr.w);
    ((float4*)g_bufA)[w * 32 + lane] = oa;
    ((float4*)g_bufB)[w * 32 + lane] = ob;
}

// ---------------- GEMM: [n x 64-row tiles] @ [128 x 128] via 3xTF32 mma -----
// Block = 64 rows, 8 warps. Warp (wid) owns 16 rows (wid>>1) x 64 cols (wid&1):
// 8 n8-tiles -> acc = 32 regs. Per 32-k chunk, weight fragments (32 KB) are
// staged into smem with coalesced LDG (8 float4/thread), then the mma loop
// reads them via conflict-free lane-indexed LDS.128. A staged in 8 KB smem.
// D += Ahi*Bhi + Ahi*Blo + Alo*Bhi  (3xTF32: fp32-grade accuracy).
// ASRC: 0=g_bufA, 1=g_bufB, 2=external (x). CDST: 0=g_bufC, 1=g_bufD, 2=g_bufE.
template<int ASRC, int CDST, int WIDX, bool RELU>
__global__ void __launch_bounds__(256, 2) gemmT(const float* __restrict__ Aext,
                                                int n) {
    const float* A = (ASRC == 0) ? g_bufA : (ASRC == 1) ? g_bufB : Aext;
    float* C       = (CDST == 0) ? g_bufC : (CDST == 1) ? g_bufD : g_bufE;
    const float4* WF = g_wf + WIDX * 8192;

    __shared__ float  sA[2048];    // 8 KB:  [rowg(4)][ks(4)][lane(32)][j(4)]
    __shared__ float4 sW[2048];    // 32 KB: [ksl(4)][tile16(16)][lane(32)]

    int tid  = threadIdx.x;
    int wid  = tid >> 5;
    int lane = tid & 31;
    int g    = lane >> 2;     // group id (row / n offset)
    int t    = lane & 3;      // thread-in-group (k offset)

    int rowg = wid >> 1;          // row group 0..3 (16 rows each)
    int ch   = wid & 1;           // column half 0..1 (64 cols each)

    int rowB = blockIdx.x * 64;
    int rA = rowB + rowg * 16 + g;
    int rB = rA + 8;
    bool v0 = rA < n, v1 = rB < n;

    float4 acc[8];
    #pragma unroll
    for (int i = 0; i < 8; i++) acc[i] = make_float4(0.f, 0.f, 0.f, 0.f);

    const float4* A4 = (const float4*)A;

    for (int chunk = 0; chunk < 4; chunk++) {
        __syncthreads();
        // ---- stage A chunk (64 rows x 32 k) coalesced -> fragment layout
        #pragma unroll
        for (int i = 0; i < 2; i++) {
            int idx = tid + i * 256;        // 0..511
            int r = idx >> 3;               // row within tile 0..63
            int q = idx & 7;                // float4 index within 32-k chunk
            float4 v = (rowB + r < n) ? A4[(rowB + r) * 32 + chunk * 8 + q]
                                      : make_float4(0.f, 0.f, 0.f, 0.f);
            int rg = r >> 4;                // row group
            int rw = r & 15;
            int gp = rw & 7, half = rw >> 3;
            #pragma unroll
            for (int j = 0; j < 4; j++) {
                int k = 4 * q + j;
                int ks = k >> 3, kk = k & 7;
                int addr = ((rg * 4 + ks) * 32 + gp * 4 + (kk & 3)) * 4
                         + (half + 2 * (kk >> 2));
                float val = (j == 0) ? v.x : (j == 1) ? v.y : (j == 2) ? v.z : v.w;
                sA[addr] = val;
            }
        }
        // ---- stage weight fragments for this chunk (2048 float4, coalesced)
        #pragma unroll
        for (int i = 0; i < 8; i++)
            sW[tid + i * 256] = WF[chunk * 2048 + tid + i * 256];
        __syncthreads();

        #pragma unroll
        for (int ksl = 0; ksl < 4; ksl++) {
            float4 a = *(const float4*)&sA[((rowg * 4 + ksl) * 32 + lane) * 4];
            float h0 = tf32r(a.x), h1 = tf32r(a.y), h2 = tf32r(a.z), h3 = tf32r(a.w);
            float l0 = tf32r(a.x - h0), l1 = tf32r(a.y - h1);
            float l2 = tf32r(a.z - h2), l3 = tf32r(a.w - h3);
            unsigned ah0 = __float_as_uint(h0), ah1 = __float_as_uint(h1);
            unsigned ah2 = __float_as_uint(h2), ah3 = __float_as_uint(h3);
            unsigned al0 = __float_as_uint(l0), al1 = __float_as_uint(l1);
            unsigned al2 = __float_as_uint(l2), al3 = __float_as_uint(l3);

            const float4* wf = sW + ksl * 512 + ch * 256 + lane;
            #pragma unroll
            for (int tile = 0; tile < 8; tile++) {
                float4 f = wf[tile * 32];
                unsigned bh0 = __float_as_uint(f.x), bh1 = __float_as_uint(f.y);
                unsigned bl0 = __float_as_uint(f.z), bl1 = __float_as_uint(f.w);
                mma8(acc[tile], ah0, ah1, ah2, ah3, bh0, bh1);   // hi*hi
                mma8(acc[tile], ah0, ah1, ah2, ah3, bl0, bl1);   // hi*lo
                mma8(acc[tile], al0, al1, al2, al3, bh0, bh1);   // lo*hi
            }
        }
    }

    // store: c0,c1 -> (rA, ch*64 + tile*8 + 2t); c2,c3 -> (rB, same cols)
    #pragma unroll
    for (int tile = 0; tile < 8; tile++) {
        float2 o0 = make_float2(acc[tile].x, acc[tile].y);
        float2 o1 = make_float2(acc[tile].z, acc[tile].w);
        if (RELU) {
            o0.x = fmaxf(o0.x, 0.f); o0.y = fmaxf(o0.y, 0.f);
            o1.x = fmaxf(o1.x, 0.f); o1.y = fmaxf(o1.y, 0.f);
        }
        int col = ch * 64 + tile * 8 + 2 * t;
        if (v0) *(float2*)(C + rA * 128 + col) = o0;
        if (v1) *(float2*)(C + rB * 128 + col) = o1;
    }
}

// ---------------- Fused epilogue: gate + relu + [128x10] projection ----------
__global__ void __launch_bounds__(256) epiK(const float* __restrict__ cc,
                                            const float* __restrict__ lam1,
                                            const float* __restrict__ lam2,
                                            const float* __restrict__ lw,
                                            const float* __restrict__ lb,
                                            float* __restrict__ out, int n) {
    __shared__ float sw[1280];
    int tid = threadIdx.x;
    for (int i = tid; i < 1280; i += 256) sw[i] = lw[i];
    __syncthreads();
    int w = (blockIdx.x << 3) + (tid >> 5);
    int lane = tid & 31;
    if (w >= n) return;

    float lamxl = 1.f / (1.f + expf(lam1[1] - lam1[0]));
    float laml  = 1.f - lamxl;
    float lamxh = 1.f / (1.f + expf(lam2[1] - lam2[0]));
    float lamh  = 1.f - lamxh;
    float m = cc[w];
    float lamx = lamxl * m + lamxh * (1.f - m);

    float4 fc = ((const float4*)g_bufE)[w * 32 + lane];
    float4 fl = ((const float4*)g_bufC)[w * 32 + lane];
    float4 fh = ((const float4*)g_bufD)[w * 32 + lane];
    float4 g;
    g.x = fmaxf(0.f, lamx * fc.x + laml * fl.x + lamh * fh.x);
    g.y = fmaxf(0.f, lamx * fc.y + laml * fl.y + lamh * fh.y);
    g.z = fmaxf(0.f, lamx * fc.z + laml * fl.z + lamh * fh.z);
    g.w = fmaxf(0.f, lamx * fc.w + laml * fl.w + lamh * fh.w);

    int base = lane * 40;  // (lane*4) * 10
    #pragma unroll
    for (int c = 0; c < 10; c++) {
        float p = g.x * sw[base + c] + g.y * sw[base + 10 + c] +
                  g.z * sw[base + 20 + c] + g.w * sw[base + 30 + c];
        #pragma unroll
        for (int off = 16; off > 0; off >>= 1)
            p += __shfl_xor_sync(0xffffffffu, p, off);
        if (lane == 0) out[w * 10 + c] = p + lb[c];
    }
}

// ---------------- Launch (kernel launches ONLY, no host API) ----------------
extern "C" void kernel_launch(void* const* d_in, const int* in_sizes, int n_in,
                              void* d_out, int out_size) {
    const float* x    = (const float*)d_in[0];
    const int*   ei   = (const int*)d_in[1];       // int32 (or int64 low-words; detected)
    const float* cc   = (const float*)d_in[2];
    const float* W1L  = (const float*)d_in[3];
    const float* W1H  = (const float*)d_in[4];
    const float* W2L  = (const float*)d_in[5];
    const float* W2H  = (const float*)d_in[6];
    const float* WX   = (const float*)d_in[7];
    const float* lam1 = (const float*)d_in[8];
    const float* lam2 = (const float*)d_in[9];
    const float* lw   = (const float*)d_in[10];
    const float* lb   = (const float*)d_in[11];
    float*       out  = (float*)d_out;

    int n = in_sizes[2];        // cc_mask element count == N
    int E = in_sizes[1] / 2;    // element count / 2, dtype-independent

    int nbN = (n + 255) / 256;
    int nbE = (E + 255) / 256;
    int nbW = (n + 7) / 8;      // warp-per-row kernels, 8 warps/block
    int nbG = (n + 63) / 64;    // GEMM 64-row tiles

    // order chosen so launch index 3 (the ncu sample) is a gemmT
    detectK<<<1, 256>>>(ei, in_sizes[1]);                       // 0
    initK<<<nbN, 256>>>(n);                                     // 1
    wprepK<<<dim3(16, 5), 256>>>(W1L, W1H, W2L, W2H, WX);       // 2
    gemmT<2, 2, 4, false><<<nbG, 256>>>(x, n);                  // 3: bufE = x@WX (profiled)
    countK<<<nbE, 256>>>(ei, cc, E, n);                         // 4
    bsumK<<<nbN, 256>>>(n);                                     // 5
    bscanK<<<1, 512>>>(nbN, n);                                 // 6
    bfinalK<<<nbN, 256>>>(n);                                   // 7
    dinvK<<<nbN, 256>>>(cc, n);                                 // 8
    scatterK<<<nbE, 256>>>(ei, E, n);                           // 9

    spmm1K<<<nbW, 256>>>(x, cc, n);                             // -> bufA, bufB
    gemmT<0, 0, 0, true ><<<nbG, 256>>>(nullptr, n);            // bufC = relu(bufA@W1L)
    gemmT<1, 1, 1, true ><<<nbG, 256>>>(nullptr, n);            // bufD = relu(bufB@W1H)
    spmm2F<<<nbW, 256>>>(n);                                    // bufA, bufB
    gemmT<0, 0, 2, false><<<nbG, 256>>>(nullptr, n);            // bufC = bufA@W2L (xl)
    gemmT<1, 1, 3, false><<<nbG, 256>>>(nullptr, n);            // bufD = bufB@W2H (xh)
    epiK<<<nbW, 256>>>(cc, lam1, lam2, lw, lb, out, n);
}

// round 15
// speedup vs baseline: 1.3930x; 1.0223x over previous
#include <cuda_runtime.h>

// ---------------- Problem constants ----------------
#define NMAX 100352          // >= 100000 nodes
#define EMAX 1700000         // >= 1.6M edges
#define FEAT 128             // F == H == 128

// ---------------- Device scratch (no allocs allowed) ----------------
__device__ int   g_is64;
__device__ int   g_oddnz;
__device__ int   g_cnt[NMAX];
__device__ float g_summ[NMAX];
__device__ int   g_rowptr[NMAX + 1];
__device__ int   g_wcur[NMAX];
__device__ int   g_colind[EMAX];
__device__ int   g_bsum[512];
__device__ int   g_boff[512];
__device__ float2 g_dlh[NMAX];            // packed (dl, dh)
__device__ float g_dll[NMAX], g_dhh[NMAX];
__device__ float g_wll[NMAX], g_whh[NMAX];
__device__ float g_bufA[NMAX * FEAT];
__device__ float g_bufB[NMAX * FEAT];
__device__ float g_bufC[NMAX * FEAT];
__device__ float g_bufD[NMAX * FEAT];
__device__ float g_bufE[NMAX * FEAT];
// weight fragments: 5 weights x 8192 float4 (16 ksteps x 16 tiles x 32 lanes)
// float4 = {hi(b0), hi(b1), lo(b0), lo(b1)}
__device__ float4 g_wf[5 * 8192];

// ---------------- tf32 helpers -----------------
__device__ __forceinline__ float tf32r(float x) {
    unsigned u;
    asm("cvt.rna.tf32.f32 %0, %1;" : "=r"(u) : "f"(x));
    return __uint_as_float(u);
}

__device__ __forceinline__ void mma8(float4& d,
                                     unsigned a0, unsigned a1, unsigned a2, unsigned a3,
                                     unsigned b0, unsigned b1) {
    asm("mma.sync.aligned.m16n8k8.row.col.f32.tf32.tf32.f32 "
        "{%0,%1,%2,%3}, {%4,%5,%6,%7}, {%8,%9}, {%0,%1,%2,%3};"
        : "+f"(d.x), "+f"(d.y), "+f"(d.z), "+f"(d.w)
        : "r"(a0), "r"(a1), "r"(a2), "r"(a3), "r"(b0), "r"(b1));
}

// ---------------- dtype detector: int32 vs int64 edge_index -------------
__global__ void detectK(const int* __restrict__ ei, int nwords) {
    if (threadIdx.x == 0) g_oddnz = 0;
    __syncthreads();
    int lim = nwords < 4096 ? nwords : 4096;
    for (int i = 1 + 2 * (int)threadIdx.x; i < lim; i += 2 * (int)blockDim.x)
        if (ei[i] != 0) atomicOr(&g_oddnz, 1);
    __syncthreads();
    if (threadIdx.x == 0) g_is64 = (g_oddnz == 0) ? 1 : 0;
}

__device__ __forceinline__ void edge_fetch(const int* ei, int E, int e,
                                           int& s, int& r) {
    if (g_is64) {          // int64 little-endian: low words at even positions
        s = ei[2 * e];
        r = ei[2 * E + 2 * e];
    } else {               // int32: [src x E, dst x E]
        s = ei[e];
        r = ei[E + e];
    }
}

// ---------------- weight fragment prep: 5 weights -> g_wf ----------------
// Fragment semantics (m16n8k8.row.col): lane = 4g+t holds
//   b0 = W[ksg*8 + t][tile*8 + g], b1 = W[ksg*8 + t + 4][tile*8 + g]
__global__ void wprepK(const float* __restrict__ W1L, const float* __restrict__ W1H,
                       const float* __restrict__ W2L, const float* __restrict__ W2H,
                       const float* __restrict__ WX) {
    const float* Ws[5] = {W1L, W1H, W2L, W2H, WX};
    int widx = blockIdx.y;
    const float* W = Ws[widx];
    int base = blockIdx.x * 512;          // 16 blocks x 512 float4 = 8192
    for (int i = 0; i < 2; i++) {
        int idx = base + threadIdx.x + i * 256;
        int lane = idx & 31;
        int tile = (idx >> 5) & 15;
        int ksg  = idx >> 9;
        int g = lane >> 2, t = lane & 3;
        float b0 = W[(ksg * 8 + t) * 128 + tile * 8 + g];
        float b1 = W[(ksg * 8 + t + 4) * 128 + tile * 8 + g];
        float h0 = tf32r(b0), h1 = tf32r(b1);
        float l0 = tf32r(b0 - h0), l1 = tf32r(b1 - h1);
        g_wf[widx * 8192 + idx] = make_float4(h0, h1, l0, l1);
    }
}

// ---------------- Preprocessing ----------------
__global__ void initK(int n) {
    int i = blockIdx.x * blockDim.x + threadIdx.x;
    if (i < n) { g_cnt[i] = 0; g_summ[i] = 0.f; }
}

__global__ void countK(const int* __restrict__ ei,
                       const float* __restrict__ cc, int E, int n) {
    int e = blockIdx.x * blockDim.x + threadIdx.x;
    if (e >= E) return;
    int s, r;
    edge_fetch(ei, E, e, s, r);
    if (s != r && (unsigned)s < (unsigned)n && (unsigned)r < (unsigned)n) {
        atomicAdd(&g_cnt[r], 1);
        atomicAdd(&g_summ[r], cc[s]);
    }
}

// ---------------- 3-phase grid scan over g_cnt -> rowptr, wcur ----------
__global__ void bsumK(int n) {
    __shared__ int sh[256];
    int t = threadIdx.x;
    int i = blockIdx.x * 256 + t;
    int v = (i < n) ? g_cnt[i] : 0;
    sh[t] = v;
    __syncthreads();
    for (int s = 128; s > 0; s >>= 1) {
        if (t < s) sh[t] += sh[t + s];
        __syncthreads();
    }
    if (t == 0) g_bsum[blockIdx.x] = sh[0];
}

__global__ void bscanK(int nb, int n) {   // 1 block, 512 threads
    __shared__ int sh[512];
    int t = threadIdx.x;
    int v = (t < nb) ? g_bsum[t] : 0;
    sh[t] = v;
    __syncthreads();
    for (int off = 1; off < 512; off <<= 1) {
        int u = (t >= off) ? sh[t - off] : 0;
        __syncthreads();
        sh[t] += u;
        __syncthreads();
    }
    g_boff[t] = sh[t] - v;                 // exclusive prefix
    if (t == 0) g_rowptr[n] = sh[511];     // grand total
}

__global__ void bfinalK(int n) {
    __shared__ int sh[256];
    int t = threadIdx.x;
    int i = blockIdx.x * 256 + t;
    int v = (i < n) ? g_cnt[i] : 0;
    sh[t] = v;
    __syncthreads();
    for (int off = 1; off < 256; off <<= 1) {
        int u = (t >= off) ? sh[t - off] : 0;
        __syncthreads();
        sh[t] += u;
        __syncthreads();
    }
    int excl = sh[t] - v + g_boff[blockIdx.x];
    if (i < n) { g_rowptr[i] = excl; g_wcur[i] = excl; }
}

__global__ void dinvK(const float* __restrict__ cc, int n) {
    int i = blockIdx.x * blockDim.x + threadIdx.x;
    if (i >= n) return;
    float m   = cc[i];
    float cnt = (float)g_cnt[i];
    float sm  = g_summ[i];
    float dl  = rsqrtf(m * cnt + 1.f);
    float dh  = rsqrtf((1.f - m) * cnt + 1.f);
    float dll = rsqrtf(sm + 1.f);
    float dhh = rsqrtf(cnt - sm + 1.f);
    g_dlh[i] = make_float2(dl, dh);
    g_dll[i] = dll; g_dhh[i] = dhh;
    g_wll[i] = m * dll;
    g_whh[i] = (1.f - m) * dhh;
}

__global__ void scatterK(const int* __restrict__ ei, int E, int n) {
    int e = blockIdx.x * blockDim.x + threadIdx.x;
    if (e >= E) return;
    int s, r;
    edge_fetch(ei, E, e, s, r);
    if (s != r && (unsigned)s < (unsigned)n && (unsigned)r < (unsigned)n) {
        int pos = atomicAdd(&g_wcur[r], 1);
        g_colind[pos] = s;
    }
}

// ---------------- SpMM layer 1: warp per destination row (fused low+high) ---
__global__ void __launch_bounds__(256) spmm1K(const float* __restrict__ x,
                                              const float* __restrict__ cc, int n) {
    int w = (blockIdx.x * blockDim.x + threadIdx.x) >> 5;
    int lane = threadIdx.x & 31;
    if (w >= n) return;
    const float4* x4 = (const float4*)x;
    float4 al = make_float4(0.f, 0.f, 0.f, 0.f);
    float4 ah = make_float4(0.f, 0.f, 0.f, 0.f);
    int s = g_rowptr[w], e = g_rowptr[w + 1];
    for (int i = s; i < e; i++) {
        int c = g_colind[i];
        float2 wlh = g_dlh[c];
        float4 xv = __ldg(&x4[c * 32 + lane]);
        al.x = fmaf(wlh.x, xv.x, al.x); al.y = fmaf(wlh.x, xv.y, al.y);
        al.z = fmaf(wlh.x, xv.z, al.z); al.w = fmaf(wlh.x, xv.w, al.w);
        ah.x = fmaf(wlh.y, xv.x, ah.x); ah.y = fmaf(wlh.y, xv.y, ah.y);
        ah.z = fmaf(wlh.y, xv.z, ah.z); ah.w = fmaf(wlh.y, xv.w, ah.w);
    }
    float m = cc[w];
    float2 dlh = g_dlh[w];
    float4 xr = x4[w * 32 + lane];
    float sl = dlh.x * m, dl2 = dlh.x * dlh.x;
    float sh = dlh.y * (1.f - m), dh2 = dlh.y * dlh.y;
    float4 ol, oh;
    ol.x = fmaf(sl, al.x, dl2 * xr.x); ol.y = fmaf(sl, al.y, dl2 * xr.y);
    ol.z = fmaf(sl, al.z, dl2 * xr.z); ol.w = fmaf(sl, al.w, dl2 * xr.w);
    oh.x = fmaf(sh, ah.x, dh2 * xr.x); oh.y = fmaf(sh, ah.y, dh2 * xr.y);
    oh.z = fmaf(sh, ah.z, dh2 * xr.z); oh.w = fmaf(sh, ah.w, dh2 * xr.w);
    ((float4*)g_bufA)[w * 32 + lane] = ol;
    ((float4*)g_bufB)[w * 32 + lane] = oh;
}

// ---------------- SpMM layer 2, fused low+high (shared index walk) ----------
__global__ void __launch_bounds__(256) spmm2F(int n) {
    int w = (blockIdx.x * blockDim.x + threadIdx.x) >> 5;
    int lane = threadIdx.x & 31;
    if (w >= n) return;
    const float4* c4 = (const float4*)g_bufC;
    const float4* d4 = (const float4*)g_bufD;
    float4 accC = make_float4(0.f, 0.f, 0.f, 0.f);
    float4 accD = make_float4(0.f, 0.f, 0.f, 0.f);
    int s = g_rowptr[w], e = g_rowptr[w + 1];
    for (int i = s; i < e; i++) {
        int c = g_colind[i];
        float wl = g_wll[c];
        float wh = g_whh[c];
        float4 cv = __ldg(&c4[c * 32 + lane]);
        float4 dv = __ldg(&d4[c * 32 + lane]);
        accC.x = fmaf(wl, cv.x, accC.x); accC.y = fmaf(wl, cv.y, accC.y);
        accC.z = fmaf(wl, cv.z, accC.z); accC.w = fmaf(wl, cv.w, accC.w);
        accD.x = fmaf(wh, dv.x, accD.x); accD.y = fmaf(wh, dv.y, accD.y);
        accD.z = fmaf(wh, dv.z, accD.z); accD.w = fmaf(wh, dv.w, accD.w);
    }
    float dl = g_dll[w], dl2 = dl * dl;
    float dh = g_dhh[w], dh2 = dh * dh;
    float4 cr = c4[w * 32 + lane];
    float4 dr = d4[w * 32 + lane];
    float4 oa, ob;
    oa.x = fmaf(dl, accC.x, dl2 * cr.x); oa.y = fmaf(dl, accC.y, dl2 * cr.y);
    oa.z = fmaf(dl, accC.z, dl2 * cr.z); oa.w = fmaf(dl, accC.w, dl2 * cr.w);
    ob.x = fmaf(dh, accD.x, dh2 * dr.x); ob.y = fmaf(dh, accD.y, dh2 * dr.y);
    ob.z = fmaf(dh, accD.z, dh2 * dr.z); ob.w = fmaf(dh, accD.w, dh2 * dr.w);
    ((float4*)g_bufA)[w * 32 + lane] = oa;
    ((float4*)g_bufB)[w * 32 + lane] = ob;
}

// ---------------- GEMM: [n x 128-row tiles] @ [128 x 128] via 3xTF32 mma ----
// Block = 128 rows, 8 warps. Warp (wid) owns 32 rows (two m16 tiles, rowg =
// wid>>1) x 64 cols (ch = wid&1): acc[2][8] float4. Both m-tiles share the
// same 8 weight fragments per k-step -> mma:LDS ratio doubles vs 16-row warp.
// Per 32-k chunk: weight fragments (32 KB) + A (16 KB) staged in smem.
// D += Ahi*Bhi + Ahi*Blo + Alo*Bhi  (3xTF32: fp32-grade accuracy).
// ASRC: 0=g_bufA, 1=g_bufB, 2=external (x). CDST: 0=g_bufC, 1=g_bufD, 2=g_bufE.
template<int ASRC, int CDST, int WIDX, bool RELU>
__global__ void __launch_bounds__(256, 2) gemmT(const float* __restrict__ Aext,
                                                int n) {
    const float* A = (ASRC == 0) ? g_bufA : (ASRC == 1) ? g_bufB : Aext;
    float* C       = (CDST == 0) ? g_bufC : (CDST == 1) ? g_bufD : g_bufE;
    const float4* WF = g_wf + WIDX * 8192;

    __shared__ float  sA[4096];    // 16 KB: [rg(8)][ks(4)][lane(32)][j(4)]
    __shared__ float4 sW[2048];    // 32 KB: [ksl(4)][tile16(16)][lane(32)]

    int tid  = threadIdx.x;
    int wid  = tid >> 5;
    int lane = tid & 31;
    int g    = lane >> 2;     // group id (row / n offset)
    int t    = lane & 3;      // thread-in-group (k offset)

    int rowg = wid >> 1;          // row group 0..3 (32 rows each)
    int ch   = wid & 1;           // column half 0..1 (64 cols each)

    int rowB = blockIdx.x * 128;
    int r0 = rowB + rowg * 32 + g;      // m-tile 0: rows r0, r0+8
    int r1 = r0 + 16;                   // m-tile 1: rows r1, r1+8
    bool v00 = r0 < n,      v01 = (r0 + 8) < n;
    bool v10 = r1 < n,      v11 = (r1 + 8) < n;

    float4 acc[2][8];
    #pragma unroll
    for (int m = 0; m < 2; m++)
        #pragma unroll
        for (int i = 0; i < 8; i++) acc[m][i] = make_float4(0.f, 0.f, 0.f, 0.f);

    const float4* A4 = (const float4*)A;

    for (int chunk = 0; chunk < 4; chunk++) {
        __syncthreads();
        // ---- stage A chunk (128 rows x 32 k) coalesced -> fragment layout
        #pragma unroll
        for (int i = 0; i < 4; i++) {
            int idx = tid + i * 256;        // 0..1023
            int r = idx >> 3;               // row within tile 0..127
            int q = idx & 7;                // float4 index within 32-k chunk
            float4 v = (rowB + r < n) ? A4[(rowB + r) * 32 + chunk * 8 + q]
                                      : make_float4(0.f, 0.f, 0.f, 0.f);
            int rg = r >> 4;                // 16-row group 0..7
            int rw = r & 15;
            int gp = rw & 7, half = rw >> 3;
            #pragma unroll
            for (int j = 0; j < 4; j++) {
                int k = 4 * q + j;
                int ks = k >> 3, kk = k & 7;
                int addr = ((rg * 4 + ks) * 32 + gp * 4 + (kk & 3)) * 4
                         + (half + 2 * (kk >> 2));
                float val = (j == 0) ? v.x : (j == 1) ? v.y : (j == 2) ? v.z : v.w;
                sA[addr] = val;
            }
        }
        // ---- stage weight fragments for this chunk (2048 float4, coalesced)
        #pragma unroll
        for (int i = 0; i < 8; i++)
            sW[tid + i * 256] = WF[chunk * 2048 + tid + i * 256];
        __syncthreads();

        #pragma unroll
        for (int ksl = 0; ksl < 4; ksl++) {
            // A fragments for the two m16 tiles (rg = rowg*2, rowg*2+1)
            float4 a0 = *(const float4*)&sA[(((rowg * 2 + 0) * 4 + ksl) * 32 + lane) * 4];
            float4 a1 = *(const float4*)&sA[(((rowg * 2 + 1) * 4 + ksl) * 32 + lane) * 4];
            unsigned ah[2][4], al[2][4];
            {
                float h0 = tf32r(a0.x), h1 = tf32r(a0.y), h2 = tf32r(a0.z), h3 = tf32r(a0.w);
                al[0][0] = __float_as_uint(tf32r(a0.x - h0));
                al[0][1] = __float_as_uint(tf32r(a0.y - h1));
                al[0][2] = __float_as_uint(tf32r(a0.z - h2));
                al[0][3] = __float_as_uint(tf32r(a0.w - h3));
                ah[0][0] = __float_as_uint(h0); ah[0][1] = __float_as_uint(h1);
                ah[0][2] = __float_as_uint(h2); ah[0][3] = __float_as_uint(h3);
            }
            {
                float h0 = tf32r(a1.x), h1 = tf32r(a1.y), h2 = tf32r(a1.z), h3 = tf32r(a1.w);
                al[1][0] = __float_as_uint(tf32r(a1.x - h0));
                al[1][1] = __float_as_uint(tf32r(a1.y - h1));
                al[1][2] = __float_as_uint(tf32r(a1.z - h2));
                al[1][3] = __float_as_uint(tf32r(a1.w - h3));
                ah[1][0] = __float_as_uint(h0); ah[1][1] = __float_as_uint(h1);
                ah[1][2] = __float_as_uint(h2); ah[1][3] = __float_as_uint(h3);
            }

            const float4* wf = sW + ksl * 512 + ch * 256 + lane;
            #pragma unroll
            for (int tile = 0; tile < 8; tile++) {
                float4 f = wf[tile * 32];
                unsigned bh0 = __float_as_uint(f.x), bh1 = __float_as_uint(f.y);
                unsigned bl0 = __float_as_uint(f.z), bl1 = __float_as_uint(f.w);
                #pragma unroll
                for (int m = 0; m < 2; m++) {
                    mma8(acc[m][tile], ah[m][0], ah[m][1], ah[m][2], ah[m][3], bh0, bh1);
                    mma8(acc[m][tile], ah[m][0], ah[m][1], ah[m][2], ah[m][3], bl0, bl1);
                    mma8(acc[m][tile], al[m][0], al[m][1], al[m][2], al[m][3], bh0, bh1);
                }
            }
        }
    }

    // store: per m-tile: c0,c1 -> (row, ch*64 + tile*8 + 2t); c2,c3 -> row+8
    #pragma unroll
    for (int m = 0; m < 2; m++) {
        int rlo = (m == 0) ? r0 : r1;
        bool vlo = (m == 0) ? v00 : v10;
        bool vhi = (m == 0) ? v01 : v11;
        #pragma unroll
        for (int tile = 0; tile < 8; tile++) {
            float2 o0 = make_float2(acc[m][tile].x, acc[m][tile].y);
            float2 o1 = make_float2(acc[m][tile].z, acc[m][tile].w);
            if (RELU) {
                o0.x = fmaxf(o0.x, 0.f); o0.y = fmaxf(o0.y, 0.f);
                o1.x = fmaxf(o1.x, 0.f); o1.y = fmaxf(o1.y, 0.f);
            }
            int col = ch * 64 + tile * 8 + 2 * t;
            if (vlo) *(float2*)(C + rlo * 128 + col) = o0;
            if (vhi) *(float2*)(C + (rlo + 8) * 128 + col) = o1;
        }
    }
}

// ---------------- Fused epilogue: gate + relu + [128x10] projection ----------
__global__ void __launch_bounds__(256) epiK(const float* __restrict__ cc,
                                            const float* __restrict__ lam1,
                                            const float* __restrict__ lam2,
                                            const float* __restrict__ lw,
                                            const float* __restrict__ lb,
                                            float* __restrict__ out, int n) {
    __shared__ float sw[1280];
    int tid = threadIdx.x;
    for (int i = tid; i < 1280; i += 256) sw[i] = lw[i];
    __syncthreads();
    int w = (blockIdx.x << 3) + (tid >> 5);
    int lane = tid & 31;
    if (w >= n) return;

    float lamxl = 1.f / (1.f + expf(lam1[1] - lam1[0]));
    float laml  = 1.f - lamxl;
    float lamxh = 1.f / (1.f + expf(lam2[1] - lam2[0]));
    float lamh  = 1.f - lamxh;
    float m = cc[w];
    float lamx = lamxl * m + lamxh * (1.f - m);

    float4 fc = ((const float4*)g_bufE)[w * 32 + lane];
    float4 fl = ((const float4*)g_bufC)[w * 32 + lane];
    float4 fh = ((const float4*)g_bufD)[w * 32 + lane];
    float4 g;
    g.x = fmaxf(0.f, lamx * fc.x + laml * fl.x + lamh * fh.x);
    g.y = fmaxf(0.f, lamx * fc.y + laml * fl.y + lamh * fh.y);
    g.z = fmaxf(0.f, lamx * fc.z + laml * fl.z + lamh * fh.z);
    g.w = fmaxf(0.f, lamx * fc.w + laml * fl.w + lamh * fh.w);

    int base = lane * 40;  // (lane*4) * 10
    #pragma unroll
    for (int c = 0; c < 10; c++) {
        float p = g.x * sw[base + c] + g.y * sw[base + 10 + c] +
                  g.z * sw[base + 20 + c] + g.w * sw[base + 30 + c];
        #pragma unroll
        for (int off = 16; off > 0; off >>= 1)
            p += __shfl_xor_sync(0xffffffffu, p, off);
        if (lane == 0) out[w * 10 + c] = p + lb[c];
    }
}

// ---------------- Launch (kernel launches ONLY, no host API) ----------------
extern "C" void kernel_launch(void* const* d_in, const int* in_sizes, int n_in,
                              void* d_out, int out_size) {
    const float* x    = (const float*)d_in[0];
    const int*   ei   = (const int*)d_in[1];       // int32 (or int64 low-words; detected)
    const float* cc   = (const float*)d_in[2];
    const float* W1L  = (const float*)d_in[3];
    const float* W1H  = (const float*)d_in[4];
    const float* W2L  = (const float*)d_in[5];
    const float* W2H  = (const float*)d_in[6];
    const float* WX   = (const float*)d_in[7];
    const float* lam1 = (const float*)d_in[8];
    const float* lam2 = (const float*)d_in[9];
    const float* lw   = (const float*)d_in[10];
    const float* lb   = (const float*)d_in[11];
    float*       out  = (float*)d_out;

    int n = in_sizes[2];        // cc_mask element count == N
    int E = in_sizes[1] / 2;    // element count / 2, dtype-independent

    int nbN = (n + 255) / 256;
    int nbE = (E + 255) / 256;
    int nbW = (n + 7) / 8;      // warp-per-row kernels, 8 warps/block
    int nbG = (n + 127) / 128;  // GEMM 128-row tiles

    // order chosen so launch index 3 (the ncu sample) is a gemmT
    detectK<<<1, 256>>>(ei, in_sizes[1]);                       // 0
    initK<<<nbN, 256>>>(n);                                     // 1
    wprepK<<<dim3(16, 5), 256>>>(W1L, W1H, W2L, W2H, WX);       // 2
    gemmT<2, 2, 4, false><<<nbG, 256>>>(x, n);                  // 3: bufE = x@WX (profiled)
    countK<<<nbE, 256>>>(ei, cc, E, n);                         // 4
    bsumK<<<nbN, 256>>>(n);                                     // 5
    bscanK<<<1, 512>>>(nbN, n);                                 // 6
    bfinalK<<<nbN, 256>>>(n);                                   // 7
    dinvK<<<nbN, 256>>>(cc, n);                                 // 8
    scatterK<<<nbE, 256>>>(ei, E, n);                           // 9

    spmm1K<<<nbW, 256>>>(x, cc, n);                             // -> bufA, bufB
    gemmT<0, 0, 0, true ><<<nbG, 256>>>(nullptr, n);            // bufC = relu(bufA@W1L)
    gemmT<1, 1, 1, true ><<<nbG, 256>>>(nullptr, n);            // bufD = relu(bufB@W1H)
    spmm2F<<<nbW, 256>>>(n);                                    // bufA, bufB
    gemmT<0, 0, 2, false><<<nbG, 256>>>(nullptr, n);            // bufC = bufA@W2L (xl)
    gemmT<1, 1, 3, false><<<nbG, 256>>>(nullptr, n);            // bufD = bufB@W2H (xh)
    epiK<<<nbW, 256>>>(cc, lam1, lam2, lw, lb, out, n);
}

// round 17
// speedup vs baseline: 1.4306x; 1.0270x over previous
#include <cuda_runtime.h>

// ---------------- Problem constants ----------------
#define NMAX 100352          // >= 100000 nodes
#define EMAX 1700000         // >= 1.6M edges
#define FEAT 128             // F == H == 128

// ---------------- Device scratch (no allocs allowed) ----------------
__device__ int   g_is64;
__device__ int   g_oddnz;
__device__ int   g_cnt[NMAX];
__device__ float g_summ[NMAX];
__device__ int   g_rowptr[NMAX + 1];
__device__ int   g_wcur[NMAX];
__device__ int   g_colind[EMAX];
__device__ int   g_bsum[512];
__device__ int   g_boff[512];
__device__ float2 g_dlh[NMAX];            // packed (dl, dh)
__device__ float g_dll[NMAX], g_dhh[NMAX];
__device__ float g_wll[NMAX], g_whh[NMAX];
__device__ float g_bufA[NMAX * FEAT];
__device__ float g_bufB[NMAX * FEAT];
__device__ float g_bufC[NMAX * FEAT];
__device__ float g_bufD[NMAX * FEAT];
__device__ float g_bufE[NMAX * FEAT];
// weight fragments: 5 weights x 8192 float4 (16 ksteps x 16 tiles x 32 lanes)
// float4 = {hi(b0), hi(b1), lo(b0), lo(b1)}
__device__ float4 g_wf[5 * 8192];

// ---------------- tf32 / async helpers -----------------
__device__ __forceinline__ float tf32r(float x) {
    unsigned u;
    asm("cvt.rna.tf32.f32 %0, %1;" : "=r"(u) : "f"(x));
    return __uint_as_float(u);
}

__device__ __forceinline__ void mma8(float4& d,
                                     unsigned a0, unsigned a1, unsigned a2, unsigned a3,
                                     unsigned b0, unsigned b1) {
    asm("mma.sync.aligned.m16n8k8.row.col.f32.tf32.tf32.f32 "
        "{%0,%1,%2,%3}, {%4,%5,%6,%7}, {%8,%9}, {%0,%1,%2,%3};"
        : "+f"(d.x), "+f"(d.y), "+f"(d.z), "+f"(d.w)
        : "r"(a0), "r"(a1), "r"(a2), "r"(a3), "r"(b0), "r"(b1));
}

__device__ __forceinline__ void cpasync16(unsigned saddr, const void* g) {
    asm volatile("cp.async.cg.shared.global [%0], [%1], 16;"
                 :: "r"(saddr), "l"(g));
}
__device__ __forceinline__ void cpcommit() {
    asm volatile("cp.async.commit_group;");
}
__device__ __forceinline__ void cpwait0() {
    asm volatile("cp.async.wait_group 0;");
}

// ---------------- dtype detector: int32 vs int64 edge_index -------------
__global__ void detectK(const int* __restrict__ ei, int nwords) {
    if (threadIdx.x == 0) g_oddnz = 0;
    __syncthreads();
    int lim = nwords < 4096 ? nwords : 4096;
    for (int i = 1 + 2 * (int)threadIdx.x; i < lim; i += 2 * (int)blockDim.x)
        if (ei[i] != 0) atomicOr(&g_oddnz, 1);
    __syncthreads();
    if (threadIdx.x == 0) g_is64 = (g_oddnz == 0) ? 1 : 0;
}

__device__ __forceinline__ void edge_fetch(const int* ei, int E, int e,
                                           int& s, int& r) {
    if (g_is64) {          // int64 little-endian: low words at even positions
        s = ei[2 * e];
        r = ei[2 * E + 2 * e];
    } else {               // int32: [src x E, dst x E]
        s = ei[e];
        r = ei[E + e];
    }
}

// ---------------- weight fragment prep: 5 weights -> g_wf ----------------
// Fragment semantics (m16n8k8.row.col): lane = 4g+t holds
//   b0 = W[ksg*8 + t][tile*8 + g], b1 = W[ksg*8 + t + 4][tile*8 + g]
__global__ void wprepK(const float* __restrict__ W1L, const float* __restrict__ W1H,
                       const float* __restrict__ W2L, const float* __restrict__ W2H,
                       const float* __restrict__ WX) {
    const float* Ws[5] = {W1L, W1H, W2L, W2H, WX};
    int widx = blockIdx.y;
    const float* W = Ws[widx];
    int base = blockIdx.x * 512;          // 16 blocks x 512 float4 = 8192
    for (int i = 0; i < 2; i++) {
        int idx = base + threadIdx.x + i * 256;
        int lane = idx & 31;
        int tile = (idx >> 5) & 15;
        int ksg  = idx >> 9;
        int g = lane >> 2, t = lane & 3;
        float b0 = W[(ksg * 8 + t) * 128 + tile * 8 + g];
        float b1 = W[(ksg * 8 + t + 4) * 128 + tile * 8 + g];
        float h0 = tf32r(b0), h1 = tf32r(b1);
        float l0 = tf32r(b0 - h0), l1 = tf32r(b1 - h1);
        g_wf[widx * 8192 + idx] = make_float4(h0, h1, l0, l1);
    }
}

// ---------------- Preprocessing ----------------
__global__ void initK(int n) {
    int i = blockIdx.x * blockDim.x + threadIdx.x;
    if (i < n) { g_cnt[i] = 0; g_summ[i] = 0.f; }
}

__global__ void countK(const int* __restrict__ ei,
                       const float* __restrict__ cc, int E, int n) {
    int e = blockIdx.x * blockDim.x + threadIdx.x;
    if (e >= E) return;
    int s, r;
    edge_fetch(ei, E, e, s, r);
    if (s != r && (unsigned)s < (unsigned)n && (unsigned)r < (unsigned)n) {
        atomicAdd(&g_cnt[r], 1);
        atomicAdd(&g_summ[r], cc[s]);
    }
}

// ---------------- 3-phase grid scan over g_cnt -> rowptr, wcur ----------
__global__ void bsumK(int n) {
    __shared__ int sh[256];
    int t = threadIdx.x;
    int i = blockIdx.x * 256 + t;
    int v = (i < n) ? g_cnt[i] : 0;
    sh[t] = v;
    __syncthreads();
    for (int s = 128; s > 0; s >>= 1) {
        if (t < s) sh[t] += sh[t + s];
        __syncthreads();
    }
    if (t == 0) g_bsum[blockIdx.x] = sh[0];
}

__global__ void bscanK(int nb, int n) {   // 1 block, 512 threads
    __shared__ int sh[512];
    int t = threadIdx.x;
    int v = (t < nb) ? g_bsum[t] : 0;
    sh[t] = v;
    __syncthreads();
    for (int off = 1; off < 512; off <<= 1) {
        int u = (t >= off) ? sh[t - off] : 0;
        __syncthreads();
        sh[t] += u;
        __syncthreads();
    }
    g_boff[t] = sh[t] - v;                 // exclusive prefix
    if (t == 0) g_rowptr[n] = sh[511];     // grand total
}

__global__ void bfinalK(int n) {
    __shared__ int sh[256];
    int t = threadIdx.x;
    int i = blockIdx.x * 256 + t;
    int v = (i < n) ? g_cnt[i] : 0;
    sh[t] = v;
    __syncthreads();
    for (int off = 1; off < 256; off <<= 1) {
        int u = (t >= off) ? sh[t - off] : 0;
        __syncthreads();
        sh[t] += u;
        __syncthreads();
    }
    int excl = sh[t] - v + g_boff[blockIdx.x];
    if (i < n) { g_rowptr[i] = excl; g_wcur[i] = excl; }
}

__global__ void dinvK(const float* __restrict__ cc, int n) {
    int i = blockIdx.x * blockDim.x + threadIdx.x;
    if (i >= n) return;
    float m   = cc[i];
    float cnt = (float)g_cnt[i];
    float sm  = g_summ[i];
    float dl  = rsqrtf(m * cnt + 1.f);
    float dh  = rsqrtf((1.f - m) * cnt + 1.f);
    float dll = rsqrtf(sm + 1.f);
    float dhh = rsqrtf(cnt - sm + 1.f);
    g_dlh[i] = make_float2(dl, dh);
    g_dll[i] = dll; g_dhh[i] = dhh;
    g_wll[i] = m * dll;
    g_whh[i] = (1.f - m) * dhh;
}

__global__ void scatterK(const int* __restrict__ ei, int E, int n) {
    int e = blockIdx.x * blockDim.x + threadIdx.x;
    if (e >= E) return;
    int s, r;
    edge_fetch(ei, E, e, s, r);
    if (s != r && (unsigned)s < (unsigned)n && (unsigned)r < (unsigned)n) {
        int pos = atomicAdd(&g_wcur[r], 1);
        g_colind[pos] = s;
    }
}

// ---------------- SpMM layer 1: warp per destination row (fused low+high) ---
__global__ void __launch_bounds__(256) spmm1K(const float* __restrict__ x,
                                              const float* __restrict__ cc, int n) {
    int w = (blockIdx.x * blockDim.x + threadIdx.x) >> 5;
    int lane = threadIdx.x & 31;
    if (w >= n) return;
    const float4* x4 = (const float4*)x;
    float4 al = make_float4(0.f, 0.f, 0.f, 0.f);
    float4 ah = make_float4(0.f, 0.f, 0.f, 0.f);
    int s = g_rowptr[w], e = g_rowptr[w + 1];
    for (int i = s; i < e; i++) {
        int c = g_colind[i];
        float2 wlh = g_dlh[c];
        float4 xv = __ldg(&x4[c * 32 + lane]);
        al.x = fmaf(wlh.x, xv.x, al.x); al.y = fmaf(wlh.x, xv.y, al.y);
        al.z = fmaf(wlh.x, xv.z, al.z); al.w = fmaf(wlh.x, xv.w, al.w);
        ah.x = fmaf(wlh.y, xv.x, ah.x); ah.y = fmaf(wlh.y, xv.y, ah.y);
        ah.z = fmaf(wlh.y, xv.z, ah.z); ah.w = fmaf(wlh.y, xv.w, ah.w);
    }
    float m = cc[w];
    float2 dlh = g_dlh[w];
    float4 xr = x4[w * 32 + lane];
    float sl = dlh.x * m, dl2 = dlh.x * dlh.x;
    float sh = dlh.y * (1.f - m), dh2 = dlh.y * dlh.y;
    float4 ol, oh;
    ol.x = fmaf(sl, al.x, dl2 * xr.x); ol.y = fmaf(sl, al.y, dl2 * xr.y);
    ol.z = fmaf(sl, al.z, dl2 * xr.z); ol.w = fmaf(sl, al.w, dl2 * xr.w);
    oh.x = fmaf(sh, ah.x, dh2 * xr.x); oh.y = fmaf(sh, ah.y, dh2 * xr.y);
    oh.z = fmaf(sh, ah.z, dh2 * xr.z); oh.w = fmaf(sh, ah.w, dh2 * xr.w);
    ((float4*)g_bufA)[w * 32 + lane] = ol;
    ((float4*)g_bufB)[w * 32 + lane] = oh;
}

// ---------------- SpMM layer 2, fused low+high (shared index walk) ----------
__global__ void __launch_bounds__(256) spmm2F(int n) {
    int w = (blockIdx.x * blockDim.x + threadIdx.x) >> 5;
    int lane = threadIdx.x & 31;
    if (w >= n) return;
    const float4* c4 = (const float4*)g_bufC;
    const float4* d4 = (const float4*)g_bufD;
    float4 accC = make_float4(0.f, 0.f, 0.f, 0.f);
    float4 accD = make_float4(0.f, 0.f, 0.f, 0.f);
    int s = g_rowptr[w], e = g_rowptr[w + 1];
    for (int i = s; i < e; i++) {
        int c = g_colind[i];
        float wl = g_wll[c];
        float wh = g_whh[c];
        float4 cv = __ldg(&c4[c * 32 + lane]);
        float4 dv = __ldg(&d4[c * 32 + lane]);
        accC.x = fmaf(wl, cv.x, accC.x); accC.y = fmaf(wl, cv.y, accC.y);
        accC.z = fmaf(wl, cv.z, accC.z); accC.w = fmaf(wl, cv.w, accC.w);
        accD.x = fmaf(wh, dv.x, accD.x); accD.y = fmaf(wh, dv.y, accD.y);
        accD.z = fmaf(wh, dv.z, accD.z); accD.w = fmaf(wh, dv.w, accD.w);
    }
    float dl = g_dll[w], dl2 = dl * dl;
    float dh = g_dhh[w], dh2 = dh * dh;
    float4 cr = c4[w * 32 + lane];
    float4 dr = d4[w * 32 + lane];
    float4 oa, ob;
    oa.x = fmaf(dl, accC.x, dl2 * cr.x); oa.y = fmaf(dl, accC.y, dl2 * cr.y);
    oa.z = fmaf(dl, accC.z, dl2 * cr.z); oa.w = fmaf(dl, accC.w, dl2 * cr.w);
    ob.x = fmaf(dh, accD.x, dh2 * dr.x); ob.y = fmaf(dh, accD.y, dh2 * dr.y);
    ob.z = fmaf(dh, accD.z, dh2 * dr.z); ob.w = fmaf(dh, accD.w, dh2 * dr.w);
    ((float4*)g_bufA)[w * 32 + lane] = oa;
    ((float4*)g_bufB)[w * 32 + lane] = ob;
}

// ---------------- GEMM: [n x 128-row tiles] @ [128 x 128] via 3xTF32 mma ----
// Block = 128 rows, 8 warps; warp owns 32 rows (two m16 tiles) x 64 cols.
// K processed in 8 chunks of 16, DOUBLE-BUFFERED:
//   sW (16 KB/buf) filled by cp.async (gmem already fragment-ordered),
//   sA (8 KB/buf) filled by LDG+STS scatter; staging of chunk c+1 overlaps
//   the mma loop of chunk c; one barrier per chunk.
// D += Ahi*Bhi + Ahi*Blo + Alo*Bhi  (3xTF32: fp32-grade accuracy).
// ASRC: 0=g_bufA, 1=g_bufB, 2=external (x). CDST: 0=g_bufC, 1=g_bufD, 2=g_bufE.
template<int ASRC, int CDST, int WIDX, bool RELU>
__global__ void __launch_bounds__(256, 2) gemmT(const float* __restrict__ Aext,
                                                int n) {
    const float* A = (ASRC == 0) ? g_bufA : (ASRC == 1) ? g_bufB : Aext;
    float* C       = (CDST == 0) ? g_bufC : (CDST == 1) ? g_bufD : g_bufE;
    const float4* WF = g_wf + WIDX * 8192;

    __shared__ float  sA[2][2048];   // 8 KB/buf: [rg8(8)][ksl(2)][lane(32)][j(4)]
    __shared__ float4 sW[2][1024];   // 16 KB/buf: [ksl(2)][tile16(16)][lane(32)]

    int tid  = threadIdx.x;
    int wid  = tid >> 5;
    int lane = tid & 31;
    int g    = lane >> 2;     // group id (row / n offset)
    int t    = lane & 3;      // thread-in-group (k offset)

    int rowg = wid >> 1;          // row group 0..3 (32 rows each)
    int ch   = wid & 1;           // column half 0..1 (64 cols each)

    int rowB = blockIdx.x * 128;
    int r0 = rowB + rowg * 32 + g;      // m-tile 0: rows r0, r0+8
    int r1 = r0 + 16;                   // m-tile 1: rows r1, r1+8
    bool v00 = r0 < n,      v01 = (r0 + 8) < n;
    bool v10 = r1 < n,      v11 = (r1 + 8) < n;

    float4 acc[2][8];
    #pragma unroll
    for (int m = 0; m < 2; m++)
        #pragma unroll
        for (int i = 0; i < 8; i++) acc[m][i] = make_float4(0.f, 0.f, 0.f, 0.f);

    const float4* A4 = (const float4*)A;

    // ---- staging lambdas (chunk = 16 k-values) ----
    auto stageW = [&](int c, int buf) {
        unsigned sbase = (unsigned)__cvta_generic_to_shared(&sW[buf][0]);
        #pragma unroll
        for (int i = 0; i < 4; i++) {
            int idx = tid + i * 256;                  // 0..1023
            cpasync16(sbase + idx * 16, WF + c * 1024 + idx);
        }
        cpcommit();
    };
    auto stageA = [&](int c, int buf) {
        #pragma unroll
        for (int i = 0; i < 2; i++) {
            int idx = tid + i * 256;        // 0..511
            int r = idx >> 2;               // row 0..127
            int q = idx & 3;                // float4 within 16-k chunk
            float4 v = (rowB + r < n) ? A4[(rowB + r) * 32 + c * 4 + q]
                                      : make_float4(0.f, 0.f, 0.f, 0.f);
            int rg = r >> 4;
            int rw = r & 15;
            int gp = rw & 7, half = rw >> 3;
            #pragma unroll
            for (int j = 0; j < 4; j++) {
                int k = 4 * q + j;          // 0..15
                int ksl = k >> 3, kk = k & 7;
                int addr = ((rg * 2 + ksl) * 32 + gp * 4 + (kk & 3)) * 4
                         + (half + 2 * (kk >> 2));
                float val = (j == 0) ? v.x : (j == 1) ? v.y : (j == 2) ? v.z : v.w;
                sA[buf][addr] = val;
            }
        }
    };

    // prologue: stage chunk 0 into buffer 0
    stageW(0, 0);
    stageA(0, 0);
    cpwait0();
    __syncthreads();

    #pragma unroll
    for (int c = 0; c < 8; c++) {
        int cur = c & 1, nxt = cur ^ 1;
        if (c < 7) {                    // stage next chunk under compute
            stageW(c + 1, nxt);
            stageA(c + 1, nxt);
        }
        #pragma unroll
        for (int ksl = 0; ksl < 2; ksl++) {
            float4 a0 = *(const float4*)&sA[cur][(((rowg * 2 + 0) * 2 + ksl) * 32 + lane) * 4];
            float4 a1 = *(const float4*)&sA[cur][(((rowg * 2 + 1) * 2 + ksl) * 32 + lane) * 4];
            unsigned ah[2][4], al[2][4];
            {
                float h0 = tf32r(a0.x), h1 = tf32r(a0.y), h2 = tf32r(a0.z), h3 = tf32r(a0.w);
                al[0][0] = __float_as_uint(tf32r(a0.x - h0));
                al[0][1] = __float_as_uint(tf32r(a0.y - h1));
                al[0][2] = __float_as_uint(tf32r(a0.z - h2));
                al[0][3] = __float_as_uint(tf32r(a0.w - h3));
                ah[0][0] = __float_as_uint(h0); ah[0][1] = __float_as_uint(h1);
                ah[0][2] = __float_as_uint(h2); ah[0][3] = __float_as_uint(h3);
            }
            {
                float h0 = tf32r(a1.x), h1 = tf32r(a1.y), h2 = tf32r(a1.z), h3 = tf32r(a1.w);
                al[1][0] = __float_as_uint(tf32r(a1.x - h0));
                al[1][1] = __float_as_uint(tf32r(a1.y - h1));
                al[1][2] = __float_as_uint(tf32r(a1.z - h2));
                al[1][3] = __float_as_uint(tf32r(a1.w - h3));
                ah[1][0] = __float_as_uint(h0); ah[1][1] = __float_as_uint(h1);
                ah[1][2] = __float_as_uint(h2); ah[1][3] = __float_as_uint(h3);
            }

            const float4* wf = &sW[cur][0] + ksl * 512 + ch * 256 + lane;
            #pragma unroll
            for (int tile = 0; tile < 8; tile++) {
                float4 f = wf[tile * 32];
                unsigned bh0 = __float_as_uint(f.x), bh1 = __float_as_uint(f.y);
                unsigned bl0 = __float_as_uint(f.z), bl1 = __float_as_uint(f.w);
                #pragma unroll
                for (int m = 0; m < 2; m++) {
                    mma8(acc[m][tile], ah[m][0], ah[m][1], ah[m][2], ah[m][3], bh0, bh1);
                    mma8(acc[m][tile], ah[m][0], ah[m][1], ah[m][2], ah[m][3], bl0, bl1);
                    mma8(acc[m][tile], al[m][0], al[m][1], al[m][2], al[m][3], bh0, bh1);
                }
            }
        }
        if (c < 7) cpwait0();
        __syncthreads();
    }

    // store: per m-tile: c0,c1 -> (row, ch*64 + tile*8 + 2t); c2,c3 -> row+8
    #pragma unroll
    for (int m = 0; m < 2; m++) {
        int rlo = (m == 0) ? r0 : r1;
        bool vlo = (m == 0) ? v00 : v10;
        bool vhi = (m == 0) ? v01 : v11;
        #pragma unroll
        for (int tile = 0; tile < 8; tile++) {
            float2 o0 = make_float2(acc[m][tile].x, acc[m][tile].y);
            float2 o1 = make_float2(acc[m][tile].z, acc[m][tile].w);
            if (RELU) {
                o0.x = fmaxf(o0.x, 0.f); o0.y = fmaxf(o0.y, 0.f);
                o1.x = fmaxf(o1.x, 0.f); o1.y = fmaxf(o1.y, 0.f);
            }
            int col = ch * 64 + tile * 8 + 2 * t;
            if (vlo) *(float2*)(C + rlo * 128 + col) = o0;
            if (vhi) *(float2*)(C + (rlo + 8) * 128 + col) = o1;
        }
    }
}

// ---------------- Fused epilogue: gate + relu + [128x10] projection ----------
__global__ void __launch_bounds__(256) epiK(const float* __restrict__ cc,
                                            const float* __restrict__ lam1,
                                            const float* __restrict__ lam2,
                                            const float* __restrict__ lw,
                                            const float* __restrict__ lb,
                                            float* __restrict__ out, int n) {
    __shared__ float sw[1280];
    int tid = threadIdx.x;
    for (int i = tid; i < 1280; i += 256) sw[i] = lw[i];
    __syncthreads();
    int w = (blockIdx.x << 3) + (tid >> 5);
    int lane = tid & 31;
    if (w >= n) return;

    float lamxl = 1.f / (1.f + expf(lam1[1] - lam1[0]));
    float laml  = 1.f - lamxl;
    float lamxh = 1.f / (1.f + expf(lam2[1] - lam2[0]));
    float lamh  = 1.f - lamxh;
    float m = cc[w];
    float lamx = lamxl * m + lamxh * (1.f - m);

    float4 fc = ((const float4*)g_bufE)[w * 32 + lane];
    float4 fl = ((const float4*)g_bufC)[w * 32 + lane];
    float4 fh = ((const float4*)g_bufD)[w * 32 + lane];
    float4 g;
    g.x = fmaxf(0.f, lamx * fc.x + laml * fl.x + lamh * fh.x);
    g.y = fmaxf(0.f, lamx * fc.y + laml * fl.y + lamh * fh.y);
    g.z = fmaxf(0.f, lamx * fc.z + laml * fl.z + lamh * fh.z);
    g.w = fmaxf(0.f, lamx * fc.w + laml * fl.w + lamh * fh.w);

    int base = lane * 40;  // (lane*4) * 10
    #pragma unroll
    for (int c = 0; c < 10; c++) {
        float p = g.x * sw[base + c] + g.y * sw[base + 10 + c] +
                  g.z * sw[base + 20 + c] + g.w * sw[base + 30 + c];
        #pragma unroll
        for (int off = 16; off > 0; off >>= 1)
            p += __shfl_xor_sync(0xffffffffu, p, off);
        if (lane == 0) out[w * 10 + c] = p + lb[c];
    }
}

// ---------------- Launch (kernel launches ONLY, no host API) ----------------
extern "C" void kernel_launch(void* const* d_in, const int* in_sizes, int n_in,
                              void* d_out, int out_size) {
    const float* x    = (const float*)d_in[0];
    const int*   ei   = (const int*)d_in[1];       // int32 (or int64 low-words; detected)
    const float* cc   = (const float*)d_in[2];
    const float* W1L  = (const float*)d_in[3];
    const float* W1H  = (const float*)d_in[4];
    const float* W2L  = (const float*)d_in[5];
    const float* W2H  = (const float*)d_in[6];
    const float* WX   = (const float*)d_in[7];
    const float* lam1 = (const float*)d_in[8];
    const float* lam2 = (const float*)d_in[9];
    const float* lw   = (const float*)d_in[10];
    const float* lb   = (const float*)d_in[11];
    float*       out  = (float*)d_out;

    int n = in_sizes[2];        // cc_mask element count == N
    int E = in_sizes[1] / 2;    // element count / 2, dtype-independent

    int nbN = (n + 255) / 256;
    int nbE = (E + 255) / 256;
    int nbW = (n + 7) / 8;      // warp-per-row kernels, 8 warps/block
    int nbG = (n + 127) / 128;  // GEMM 128-row tiles

    // order chosen so launch index 3 (the ncu sample) is a gemmT
    detectK<<<1, 256>>>(ei, in_sizes[1]);                       // 0
    initK<<<nbN, 256>>>(n);                                     // 1
    wprepK<<<dim3(16, 5), 256>>>(W1L, W1H, W2L, W2H, WX);       // 2
    gemmT<2, 2, 4, false><<<nbG, 256>>>(x, n);                  // 3: bufE = x@WX (profiled)
    countK<<<nbE, 256>>>(ei, cc, E, n);                         // 4
    bsumK<<<nbN, 256>>>(n);                                     // 5
    bscanK<<<1, 512>>>(nbN, n);                                 // 6
    bfinalK<<<nbN, 256>>>(n);                                   // 7
    dinvK<<<nbN, 256>>>(cc, n);                                 // 8
    scatterK<<<nbE, 256>>>(ei, E, n);                           // 9

    spmm1K<<<nbW, 256>>>(x, cc, n);                             // -> bufA, bufB
    gemmT<0, 0, 0, true ><<<nbG, 256>>>(nullptr, n);            // bufC = relu(bufA@W1L)
    gemmT<1, 1, 1, true ><<<nbG, 256>>>(nullptr, n);            // bufD = relu(bufB@W1H)
    spmm2F<<<nbW, 256>>>(n);                                    // bufA, bufB
    gemmT<0, 0, 2, false><<<nbG, 256>>>(nullptr, n);            // bufC = bufA@W2L (xl)
    gemmT<1, 1, 3, false><<<nbG, 256>>>(nullptr, n);            // bufD = bufB@W2H (xh)
    epiK<<<nbW, 256>>>(cc, lam1, lam2, lw, lb, out, n);
}